// round 10
// baseline (speedup 1.0000x reference)
#include <cuda_runtime.h>
#include <math.h>

#define BDIM 32
#define TDIM 32
#define IDIM 256
#define HDIM 512
#define HS 64
#define MS 2048
#define NHEADS 4
#define ODIM 256
#define NKEYS 8          // 4 read + 4 write
#define LCHUNKS 32       // logits chunks per batch (64 rows each)

// ---------------- persistent state (no allocations allowed) ----------------
__device__ float g_h[2][BDIM * HDIM];
__device__ float g_c[BDIM * HDIM];
__device__ float g_read[BDIM * NHEADS * HS];
__device__ float g_rk[BDIM * NHEADS * HS];
__device__ float g_wk[BDIM * NHEADS * HS];
__device__ float g_ws[BDIM * NHEADS];
__device__ float g_logits[BDIM * NKEYS * MS];
__device__ float g_pmax[BDIM * NKEYS * LCHUNKS];
__device__ float g_psum[BDIM * NKEYS * LCHUNKS];
__device__ float g_rpart[BDIM * 32 * NHEADS * HS];
__device__ unsigned g_cnt[BDIM];   // zero-init; reset by last block each step

__device__ __forceinline__ float sigmoidf_(float x) { return 1.f / (1.f + expf(-x)); }

// ---------------- init ----------------
__global__ void k_init(float* __restrict__ mem) {
    int idx = blockIdx.x * 256 + threadIdx.x;
    if (idx < BDIM * HDIM) { g_h[0][idx] = 0.f; g_c[idx] = 0.f; }
    if (idx < BDIM * NHEADS * HS) g_read[idx] = 0.f;
    if (idx < BDIM * MS * HS) mem[idx] = 0.f;
}

// ---------------- out(t-1) body (used inside fused lstm kernel + final) ----------------
__device__ __forceinline__ void out_body(
    const float* __restrict__ W_out, const float* __restrict__ b_out,
    float* __restrict__ out, const float* __restrict__ h_prev, int t, int og, int bg)
{
    __shared__ float cat_s[8][768];
    int tid = threadIdx.x;
    int bb0 = bg * 8;
    for (int idx = tid; idx < 8 * 768; idx += 256) {
        int bb = idx / 768, k = idx % 768;
        cat_s[bb][k] = (k < 512) ? h_prev[(bb0 + bb) * HDIM + k]
                                 : g_read[(bb0 + bb) * 256 + (k - 512)];
    }
    __syncthreads();
    int w = tid >> 5, lane = tid & 31;
    int o = og * 8 + w;
    float acc[8];
#pragma unroll
    for (int bb = 0; bb < 8; bb++) acc[bb] = 0.f;
#pragma unroll
    for (int c = 0; c < 6; c++) {
        int kw = c * 128 + lane * 4;
        float4 w4 = *(const float4*)&W_out[(size_t)o * 768 + kw];
#pragma unroll
        for (int bb = 0; bb < 8; bb++) {
            float4 a4 = *(const float4*)&cat_s[bb][kw];
            acc[bb] = fmaf(w4.x, a4.x, acc[bb]);
            acc[bb] = fmaf(w4.y, a4.y, acc[bb]);
            acc[bb] = fmaf(w4.z, a4.z, acc[bb]);
            acc[bb] = fmaf(w4.w, a4.w, acc[bb]);
        }
    }
    float res = 0.f;
#pragma unroll
    for (int bb = 0; bb < 8; bb++) {
        float v = acc[bb];
        v += __shfl_xor_sync(0xffffffffu, v, 16);
        v += __shfl_xor_sync(0xffffffffu, v, 8);
        v += __shfl_xor_sync(0xffffffffu, v, 4);
        v += __shfl_xor_sync(0xffffffffu, v, 2);
        v += __shfl_xor_sync(0xffffffffu, v, 1);
        if (lane == bb) res = v;
    }
    if (lane < 8) {
        int b = bb0 + lane;
        out[((size_t)b * TDIM + t) * ODIM + o] = res + b_out[o];
    }
}

// ---------------- K1: gate GEMM + LSTM cell, out(t-1) fused as extra blocks ----------------
__global__ void __launch_bounds__(256) k_lstm(
    const float* __restrict__ x, const float* __restrict__ W_ih,
    const float* __restrict__ W_hh, const float* __restrict__ b_ih,
    const float* __restrict__ b_hh, const float* __restrict__ W_out,
    const float* __restrict__ b_out, float* __restrict__ out, int p, int t)
{
    if (blockIdx.x >= 64) {   // out(t-1) blocks (only launched when t>0)
        out_body(W_out, b_out, out, g_h[p], t - 1, blockIdx.x - 64, blockIdx.y);
        return;
    }
    __shared__ float inp_s[8][1024];
    const float* __restrict__ h_prev = g_h[p];
    float* __restrict__ h_new = g_h[p ^ 1];
    int tid = threadIdx.x;
    int bb0 = blockIdx.y * 8;
    for (int idx = tid; idx < 8 * 1024; idx += 256) {
        int bb = idx >> 10, k = idx & 1023;
        int b = bb0 + bb;
        float v;
        if (k < 256)      v = x[(b * TDIM + t) * IDIM + k];
        else if (k < 512) v = g_read[b * 256 + (k - 256)];
        else              v = h_prev[b * HDIM + (k - 512)];
        inp_s[bb][k] = v;
    }
    __syncthreads();
    int w = tid >> 5, lane = tid & 31;
    int j = blockIdx.x * 8 + w;
    float acc[4][8];
#pragma unroll
    for (int g = 0; g < 4; g++)
#pragma unroll
        for (int bb = 0; bb < 8; bb++) acc[g][bb] = 0.f;

#pragma unroll
    for (int c = 0; c < 8; c++) {
        const float* Wsrc = (c < 4) ? W_ih : W_hh;
        int kw = ((c & 3) * 128) + lane * 4;
        float4 w4[4];
#pragma unroll
        for (int g = 0; g < 4; g++)
            w4[g] = *(const float4*)&Wsrc[(size_t)(g * HDIM + j) * HDIM + kw];
        int ks = c * 128 + lane * 4;
#pragma unroll
        for (int bb = 0; bb < 8; bb++) {
            float4 a4 = *(const float4*)&inp_s[bb][ks];
#pragma unroll
            for (int g = 0; g < 4; g++) {
                acc[g][bb] = fmaf(w4[g].x, a4.x, acc[g][bb]);
                acc[g][bb] = fmaf(w4[g].y, a4.y, acc[g][bb]);
                acc[g][bb] = fmaf(w4[g].z, a4.z, acc[g][bb]);
                acc[g][bb] = fmaf(w4[g].w, a4.w, acc[g][bb]);
            }
        }
    }
    float res = 0.f;
#pragma unroll
    for (int g = 0; g < 4; g++)
#pragma unroll
        for (int bb = 0; bb < 8; bb++) {
            float v = acc[g][bb];
            v += __shfl_xor_sync(0xffffffffu, v, 16);
            v += __shfl_xor_sync(0xffffffffu, v, 8);
            v += __shfl_xor_sync(0xffffffffu, v, 4);
            v += __shfl_xor_sync(0xffffffffu, v, 2);
            v += __shfl_xor_sync(0xffffffffu, v, 1);
            if (lane == g * 8 + bb) res = v;
        }
    int bb = lane & 7;
    float iv = __shfl_sync(0xffffffffu, res, bb);
    float fv = __shfl_sync(0xffffffffu, res, 8 + bb);
    float gv = __shfl_sync(0xffffffffu, res, 16 + bb);
    float ov = __shfl_sync(0xffffffffu, res, 24 + bb);
    if (lane < 8) {
        int b = bb0 + lane;
        iv += b_ih[j] + b_hh[j];
        fv += b_ih[HDIM + j] + b_hh[HDIM + j];
        gv += b_ih[2 * HDIM + j] + b_hh[2 * HDIM + j];
        ov += b_ih[3 * HDIM + j] + b_hh[3 * HDIM + j];
        float cold = g_c[b * HDIM + j];
        float cn = sigmoidf_(fv) * cold + sigmoidf_(iv) * tanhf(gv);
        float hn = sigmoidf_(ov) * tanhf(cn);
        g_c[b * HDIM + j] = cn;
        h_new[b * HDIM + j] = hn;
    }
}

// ---------------- K2: head projection (129 used columns per head) ----------------
__global__ void __launch_bounds__(256) k_head(
    const float* __restrict__ W_head, const float* __restrict__ b_head, int pn)
{
    __shared__ float h_s[8][512];
    const float* __restrict__ h_new = g_h[pn];
    int tid = threadIdx.x;
    int bb0 = blockIdx.y * 8;
    for (int idx = tid; idx < 8 * 512; idx += 256) {
        int bb = idx >> 9, k = idx & 511;
        h_s[bb][k] = h_new[(bb0 + bb) * HDIM + k];
    }
    __syncthreads();
    int w = tid >> 5, lane = tid & 31;
    int r = blockIdx.x * 8 + w;
    if (r >= NHEADS * 129) return;
    int n = r / 129, jj = r % 129;
    int wrow = n * 2115 + jj;
    float acc[8];
#pragma unroll
    for (int bb = 0; bb < 8; bb++) acc[bb] = 0.f;
#pragma unroll
    for (int c = 0; c < 4; c++) {
        int kw = c * 128 + lane * 4;
        float4 w4 = *(const float4*)&W_head[(size_t)wrow * HDIM + kw];
#pragma unroll
        for (int bb = 0; bb < 8; bb++) {
            float4 a4 = *(const float4*)&h_s[bb][kw];
            acc[bb] = fmaf(w4.x, a4.x, acc[bb]);
            acc[bb] = fmaf(w4.y, a4.y, acc[bb]);
            acc[bb] = fmaf(w4.z, a4.z, acc[bb]);
            acc[bb] = fmaf(w4.w, a4.w, acc[bb]);
        }
    }
    float res = 0.f;
#pragma unroll
    for (int bb = 0; bb < 8; bb++) {
        float v = acc[bb];
        v += __shfl_xor_sync(0xffffffffu, v, 16);
        v += __shfl_xor_sync(0xffffffffu, v, 8);
        v += __shfl_xor_sync(0xffffffffu, v, 4);
        v += __shfl_xor_sync(0xffffffffu, v, 2);
        v += __shfl_xor_sync(0xffffffffu, v, 1);
        if (lane == bb) res = v;
    }
    if (lane < 8) {
        int b = bb0 + lane;
        float val = res + b_head[wrow];
        if (jj < HS)          g_rk[(b * NHEADS + n) * HS + jj] = val;
        else if (jj < 2 * HS) g_wk[(b * NHEADS + n) * HS + (jj - HS)] = val;
        else                  g_ws[b * NHEADS + n] = sigmoidf_(val);
    }
}

// ---------------- K3: logits — quarter-row threads, front-batched loads ----------------
// grid (32, 32): 64-row chunk, batch. thread = (row=tid>>2, quarter=tid&3).
__global__ void __launch_bounds__(256) k_logits(const float* __restrict__ mem)
{
    __shared__ __align__(16) float key_s[NKEYS][64];
    __shared__ float wred[NKEYS][8];
    __shared__ float bmax[NKEYS];
    int tid = threadIdx.x;
    int b = blockIdx.y, chunk = blockIdx.x;
    for (int idx = tid; idx < NKEYS * 64; idx += 256) {
        int key = idx >> 6, h = idx & 63, n = key & 3;
        key_s[key][h] = (key < 4) ? g_rk[(b * NHEADS + n) * HS + h]
                                  : g_wk[(b * NHEADS + n) * HS + h];
    }
    __syncthreads();

    int r = tid >> 2, q = tid & 3;
    int m = chunk * 64 + r;
    const float4* mrow = (const float4*)&mem[((size_t)b * MS + m) * HS] + q * 4;
    // front-batched loads: 4 independent LDG.128
    float4 a0 = mrow[0], a1 = mrow[1], a2 = mrow[2], a3 = mrow[3];

    float acc[NKEYS];
#pragma unroll
    for (int k = 0; k < NKEYS; k++) {
        const float4* kv = (const float4*)key_s[k] + q * 4;
        float4 k0 = kv[0], k1 = kv[1], k2 = kv[2], k3 = kv[3];
        float s = a0.x * k0.x;
        s = fmaf(a0.y, k0.y, s); s = fmaf(a0.z, k0.z, s); s = fmaf(a0.w, k0.w, s);
        s = fmaf(a1.x, k1.x, s); s = fmaf(a1.y, k1.y, s);
        s = fmaf(a1.z, k1.z, s); s = fmaf(a1.w, k1.w, s);
        s = fmaf(a2.x, k2.x, s); s = fmaf(a2.y, k2.y, s);
        s = fmaf(a2.z, k2.z, s); s = fmaf(a2.w, k2.w, s);
        s = fmaf(a3.x, k3.x, s); s = fmaf(a3.y, k3.y, s);
        s = fmaf(a3.z, k3.z, s); s = fmaf(a3.w, k3.w, s);
        acc[k] = s;
    }
    // quartet reduce (lanes sharing a row) + scale; all 4 lanes end with full logit
    const float scale = 0.125f;
#pragma unroll
    for (int k = 0; k < NKEYS; k++) {
        float v = acc[k];
        v += __shfl_xor_sync(0xffffffffu, v, 1);
        v += __shfl_xor_sync(0xffffffffu, v, 2);
        acc[k] = v * scale;
    }
    // each lane stores 2 keys (k = q and q+4): coalesced within key planes
    g_logits[((size_t)b * NKEYS + q) * MS + m] = acc[q];
    g_logits[((size_t)b * NKEYS + q + 4) * MS + m] = acc[q + 4];

    // block softmax partials: warp covers 8 rows (each row duplicated on 4 lanes)
    int w = tid >> 5, lane = tid & 31;
#pragma unroll
    for (int k = 0; k < NKEYS; k++) {
        float v = acc[k];
        v = fmaxf(v, __shfl_xor_sync(0xffffffffu, v, 4));
        v = fmaxf(v, __shfl_xor_sync(0xffffffffu, v, 8));
        v = fmaxf(v, __shfl_xor_sync(0xffffffffu, v, 16));
        if (lane == 0) wred[k][w] = v;
    }
    __syncthreads();
    if (tid < NKEYS) {
        float v = wred[tid][0];
#pragma unroll
        for (int i = 1; i < 8; i++) v = fmaxf(v, wred[tid][i]);
        bmax[tid] = v;
    }
    __syncthreads();
#pragma unroll
    for (int k = 0; k < NKEYS; k++) {
        float v = expf(acc[k] - bmax[k]);
        v += __shfl_xor_sync(0xffffffffu, v, 1);
        v += __shfl_xor_sync(0xffffffffu, v, 2);
        v += __shfl_xor_sync(0xffffffffu, v, 4);
        v += __shfl_xor_sync(0xffffffffu, v, 8);
        v += __shfl_xor_sync(0xffffffffu, v, 16);
        if (lane == 0) wred[k][w] = v * 0.25f;   // each row counted 4x (exact dup)
    }
    __syncthreads();
    if (tid < NKEYS) {
        float s = 0.f;
#pragma unroll
        for (int i = 0; i < 8; i++) s += wred[tid][i];
        g_pmax[(b * NKEYS + tid) * LCHUNKS + chunk] = bmax[tid];
        g_psum[(b * NKEYS + tid) * LCHUNKS + chunk] = s;
    }
}

// ---------------- K4: softmax finalize + single-pass read/update + last-block reduce ----------------
// grid (32, 32): chunk of 64 rows, batch.
__global__ void __launch_bounds__(256) k_attend(float* __restrict__ mem)
{
    __shared__ float gm[NKEYS], ginv[NKEYS];
    __shared__ float w_s[NKEYS][64];
    __shared__ float swk_s[NHEADS][64];
    __shared__ float sred[4][NHEADS * 64];
    __shared__ unsigned is_last;
    int tid = threadIdx.x;
    int chunk = blockIdx.x, b = blockIdx.y;

    if (tid < NKEYS) {
        const float* pm = &g_pmax[(b * NKEYS + tid) * LCHUNKS];
        const float* ps = &g_psum[(b * NKEYS + tid) * LCHUNKS];
        float m0 = pm[0];
#pragma unroll
        for (int i = 1; i < LCHUNKS; i++) m0 = fmaxf(m0, pm[i]);
        float s = 0.f;
#pragma unroll
        for (int i = 0; i < LCHUNKS; i++) s += expf(pm[i] - m0) * ps[i];
        gm[tid] = m0;
        ginv[tid] = 1.f / s;
    }
    {
        int n = tid >> 6, h = tid & 63;
        swk_s[n][h] = g_ws[b * NHEADS + n] * g_wk[(b * NHEADS + n) * HS + h];
    }
    __syncthreads();
    for (int idx = tid; idx < NKEYS * 64; idx += 256) {
        int key = idx >> 6, row = idx & 63;
        float lg = g_logits[((size_t)b * NKEYS + key) * MS + chunk * 64 + row];
        w_s[key][row] = expf(lg - gm[key]) * ginv[key];
    }
    __syncthreads();

    int h = tid & 63, ms = tid >> 6;
    float v[16];
    // front-batched loads (independent of FMA chain)
#pragma unroll
    for (int mi = 0; mi < 16; mi++) {
        int row = mi * 4 + ms;
        v[mi] = mem[((size_t)b * MS + chunk * 64 + row) * HS + h];
    }
    float acc[NHEADS] = {0.f, 0.f, 0.f, 0.f};
#pragma unroll
    for (int mi = 0; mi < 16; mi++) {
        int row = mi * 4 + ms;
#pragma unroll
        for (int n = 0; n < NHEADS; n++)
            acc[n] = fmaf(w_s[n][row], v[mi], acc[n]);
    }
#pragma unroll
    for (int mi = 0; mi < 16; mi++) {
        int row = mi * 4 + ms;
        float val = v[mi];
#pragma unroll
        for (int n = 0; n < NHEADS; n++)
            val = fmaf(w_s[4 + n][row], swk_s[n][h], val);
        mem[((size_t)b * MS + chunk * 64 + row) * HS + h] = val;
    }
#pragma unroll
    for (int n = 0; n < NHEADS; n++) sred[ms][n * 64 + h] = acc[n];
    __syncthreads();
    float tot = sred[0][tid] + sred[1][tid] + sred[2][tid] + sred[3][tid];
    g_rpart[((size_t)b * 32 + chunk) * 256 + tid] = tot;

    // deterministic last-block reduction into g_read
    __threadfence();
    if (tid == 0) is_last = (atomicAdd(&g_cnt[b], 1u) == 31u) ? 1u : 0u;
    __syncthreads();
    if (is_last) {
        if (tid == 0) g_cnt[b] = 0u;   // reset for next step / next replay
        __threadfence();
        float s = 0.f;
#pragma unroll
        for (int ch = 0; ch < 32; ch++)
            s += g_rpart[((size_t)b * 32 + ch) * 256 + tid];
        g_read[b * 256 + tid] = s;
    }
}

// ---------------- final: out(31) + state copy ----------------
__global__ void __launch_bounds__(256) k_last(
    const float* __restrict__ W_out, const float* __restrict__ b_out,
    float* __restrict__ out, float* __restrict__ dst_h, float* __restrict__ dst_c)
{
    if (blockIdx.x < 32) {
        out_body(W_out, b_out, out, g_h[0], TDIM - 1, blockIdx.x, blockIdx.y);
    } else if (blockIdx.y == 0) {
        int idx = (blockIdx.x - 32) * 256 + threadIdx.x;
        if (idx < BDIM * HDIM) {
            dst_h[idx] = g_h[0][idx];   // after 32 steps h lives in buffer 0
            dst_c[idx] = g_c[idx];
        }
    }
}

// ---------------- launch ----------------
extern "C" void kernel_launch(void* const* d_in, const int* in_sizes, int n_in,
                              void* d_out, int out_size)
{
    const float* x      = (const float*)d_in[0];
    const float* W_ih   = (const float*)d_in[1];
    const float* W_hh   = (const float*)d_in[2];
    const float* b_ih   = (const float*)d_in[3];
    const float* b_hh   = (const float*)d_in[4];
    const float* W_head = (const float*)d_in[5];
    const float* b_head = (const float*)d_in[6];
    const float* W_out  = (const float*)d_in[7];
    const float* b_out  = (const float*)d_in[8];

    float* out   = (float*)d_out;                 // (B, T, O)
    float* mem   = out + BDIM * TDIM * ODIM;      // (B, MS, HS)
    float* out_h = mem + (size_t)BDIM * MS * HS;  // (B, H)
    float* out_c = out_h + BDIM * HDIM;           // (B, H)

    k_init<<<(BDIM * MS * HS) / 256, 256>>>(mem);

    for (int t = 0; t < TDIM; t++) {
        int p = t & 1;
        int pn = p ^ 1;
        int gx = (t > 0) ? 96 : 64;   // fuse out(t-1) blocks when t>0
        k_lstm<<<dim3(gx, 4), 256>>>(x, W_ih, W_hh, b_ih, b_hh,
                                     W_out, b_out, out, p, t);
        k_head<<<dim3(65, 4), 256>>>(W_head, b_head, pn);
        k_logits<<<dim3(LCHUNKS, 32), 256>>>(mem);
        k_attend<<<dim3(32, 32), 256>>>(mem);
    }
    k_last<<<dim3(96, 4), 256>>>(W_out, b_out, out, out_h, out_c);
}

// round 11
// speedup vs baseline: 1.1308x; 1.1308x over previous
#include <cuda_runtime.h>
#include <math.h>

#define BDIM 32
#define TDIM 32
#define IDIM 256
#define HDIM 512
#define HS 64
#define MS 2048
#define NHEADS 4
#define ODIM 256
#define NKEYS 8          // 4 read + 4 write
#define LCHUNKS 16       // logits chunks per batch (128 rows each)
#define TSTRIDE 68       // padded smem row stride (floats) -> kills bank conflicts

// ---------------- persistent state (no allocations allowed) ----------------
__device__ float g_h[2][BDIM * HDIM];
__device__ float g_c[BDIM * HDIM];
__device__ float g_read[BDIM * NHEADS * HS];
__device__ float g_rk[BDIM * NHEADS * HS];
__device__ float g_wk[BDIM * NHEADS * HS];
__device__ float g_ws[BDIM * NHEADS];
__device__ float g_logits[BDIM * NKEYS * MS];
__device__ float g_pmax[BDIM * NKEYS * LCHUNKS];
__device__ float g_psum[BDIM * NKEYS * LCHUNKS];
__device__ float g_rpart[BDIM * 32 * NHEADS * HS];
__device__ unsigned g_cnt[BDIM];   // zero-init; reset by last block each step

__device__ __forceinline__ float sigmoidf_(float x) { return 1.f / (1.f + expf(-x)); }

// ---------------- init ----------------
__global__ void k_init(float* __restrict__ mem) {
    int idx = blockIdx.x * 256 + threadIdx.x;
    if (idx < BDIM * HDIM) { g_h[0][idx] = 0.f; g_c[idx] = 0.f; }
    if (idx < BDIM * NHEADS * HS) g_read[idx] = 0.f;
    if (idx < BDIM * MS * HS) mem[idx] = 0.f;
}

// ---------------- out(t-1) body (used inside fused lstm kernel + final) ----------------
__device__ __forceinline__ void out_body(
    const float* __restrict__ W_out, const float* __restrict__ b_out,
    float* __restrict__ out, const float* __restrict__ h_prev, int t, int og, int bg)
{
    __shared__ float cat_s[8][768];
    int tid = threadIdx.x;
    int bb0 = bg * 8;
    for (int idx = tid; idx < 8 * 768; idx += 256) {
        int bb = idx / 768, k = idx % 768;
        cat_s[bb][k] = (k < 512) ? h_prev[(bb0 + bb) * HDIM + k]
                                 : g_read[(bb0 + bb) * 256 + (k - 512)];
    }
    __syncthreads();
    int w = tid >> 5, lane = tid & 31;
    int o = og * 8 + w;
    float acc[8];
#pragma unroll
    for (int bb = 0; bb < 8; bb++) acc[bb] = 0.f;
#pragma unroll
    for (int c = 0; c < 6; c++) {
        int kw = c * 128 + lane * 4;
        float4 w4 = *(const float4*)&W_out[(size_t)o * 768 + kw];
#pragma unroll
        for (int bb = 0; bb < 8; bb++) {
            float4 a4 = *(const float4*)&cat_s[bb][kw];
            acc[bb] = fmaf(w4.x, a4.x, acc[bb]);
            acc[bb] = fmaf(w4.y, a4.y, acc[bb]);
            acc[bb] = fmaf(w4.z, a4.z, acc[bb]);
            acc[bb] = fmaf(w4.w, a4.w, acc[bb]);
        }
    }
    float res = 0.f;
#pragma unroll
    for (int bb = 0; bb < 8; bb++) {
        float v = acc[bb];
        v += __shfl_xor_sync(0xffffffffu, v, 16);
        v += __shfl_xor_sync(0xffffffffu, v, 8);
        v += __shfl_xor_sync(0xffffffffu, v, 4);
        v += __shfl_xor_sync(0xffffffffu, v, 2);
        v += __shfl_xor_sync(0xffffffffu, v, 1);
        if (lane == bb) res = v;
    }
    if (lane < 8) {
        int b = bb0 + lane;
        out[((size_t)b * TDIM + t) * ODIM + o] = res + b_out[o];
    }
}

// ---------------- K1: gate GEMM + LSTM cell, out(t-1) fused as extra blocks ----------------
__global__ void __launch_bounds__(256) k_lstm(
    const float* __restrict__ x, const float* __restrict__ W_ih,
    const float* __restrict__ W_hh, const float* __restrict__ b_ih,
    const float* __restrict__ b_hh, const float* __restrict__ W_out,
    const float* __restrict__ b_out, float* __restrict__ out, int p, int t)
{
    if (blockIdx.x >= 64) {   // out(t-1) blocks (only launched when t>0)
        out_body(W_out, b_out, out, g_h[p], t - 1, blockIdx.x - 64, blockIdx.y);
        return;
    }
    __shared__ float inp_s[8][1024];
    const float* __restrict__ h_prev = g_h[p];
    float* __restrict__ h_new = g_h[p ^ 1];
    int tid = threadIdx.x;
    int bb0 = blockIdx.y * 8;
    for (int idx = tid; idx < 8 * 1024; idx += 256) {
        int bb = idx >> 10, k = idx & 1023;
        int b = bb0 + bb;
        float v;
        if (k < 256)      v = x[(b * TDIM + t) * IDIM + k];
        else if (k < 512) v = g_read[b * 256 + (k - 256)];
        else              v = h_prev[b * HDIM + (k - 512)];
        inp_s[bb][k] = v;
    }
    __syncthreads();
    int w = tid >> 5, lane = tid & 31;
    int j = blockIdx.x * 8 + w;
    float acc[4][8];
#pragma unroll
    for (int g = 0; g < 4; g++)
#pragma unroll
        for (int bb = 0; bb < 8; bb++) acc[g][bb] = 0.f;

#pragma unroll
    for (int c = 0; c < 8; c++) {
        const float* Wsrc = (c < 4) ? W_ih : W_hh;
        int kw = ((c & 3) * 128) + lane * 4;
        float4 w4[4];
#pragma unroll
        for (int g = 0; g < 4; g++)
            w4[g] = *(const float4*)&Wsrc[(size_t)(g * HDIM + j) * HDIM + kw];
        int ks = c * 128 + lane * 4;
#pragma unroll
        for (int bb = 0; bb < 8; bb++) {
            float4 a4 = *(const float4*)&inp_s[bb][ks];
#pragma unroll
            for (int g = 0; g < 4; g++) {
                acc[g][bb] = fmaf(w4[g].x, a4.x, acc[g][bb]);
                acc[g][bb] = fmaf(w4[g].y, a4.y, acc[g][bb]);
                acc[g][bb] = fmaf(w4[g].z, a4.z, acc[g][bb]);
                acc[g][bb] = fmaf(w4[g].w, a4.w, acc[g][bb]);
            }
        }
    }
    float res = 0.f;
#pragma unroll
    for (int g = 0; g < 4; g++)
#pragma unroll
        for (int bb = 0; bb < 8; bb++) {
            float v = acc[g][bb];
            v += __shfl_xor_sync(0xffffffffu, v, 16);
            v += __shfl_xor_sync(0xffffffffu, v, 8);
            v += __shfl_xor_sync(0xffffffffu, v, 4);
            v += __shfl_xor_sync(0xffffffffu, v, 2);
            v += __shfl_xor_sync(0xffffffffu, v, 1);
            if (lane == g * 8 + bb) res = v;
        }
    int bb = lane & 7;
    float iv = __shfl_sync(0xffffffffu, res, bb);
    float fv = __shfl_sync(0xffffffffu, res, 8 + bb);
    float gv = __shfl_sync(0xffffffffu, res, 16 + bb);
    float ov = __shfl_sync(0xffffffffu, res, 24 + bb);
    if (lane < 8) {
        int b = bb0 + lane;
        iv += b_ih[j] + b_hh[j];
        fv += b_ih[HDIM + j] + b_hh[HDIM + j];
        gv += b_ih[2 * HDIM + j] + b_hh[2 * HDIM + j];
        ov += b_ih[3 * HDIM + j] + b_hh[3 * HDIM + j];
        float cold = g_c[b * HDIM + j];
        float cn = sigmoidf_(fv) * cold + sigmoidf_(iv) * tanhf(gv);
        float hn = sigmoidf_(ov) * tanhf(cn);
        g_c[b * HDIM + j] = cn;
        h_new[b * HDIM + j] = hn;
    }
}

// ---------------- K2: head projection (129 used columns per head) ----------------
__global__ void __launch_bounds__(256) k_head(
    const float* __restrict__ W_head, const float* __restrict__ b_head, int pn)
{
    __shared__ float h_s[8][512];
    const float* __restrict__ h_new = g_h[pn];
    int tid = threadIdx.x;
    int bb0 = blockIdx.y * 8;
    for (int idx = tid; idx < 8 * 512; idx += 256) {
        int bb = idx >> 9, k = idx & 511;
        h_s[bb][k] = h_new[(bb0 + bb) * HDIM + k];
    }
    __syncthreads();
    int w = tid >> 5, lane = tid & 31;
    int r = blockIdx.x * 8 + w;
    if (r >= NHEADS * 129) return;
    int n = r / 129, jj = r % 129;
    int wrow = n * 2115 + jj;
    float acc[8];
#pragma unroll
    for (int bb = 0; bb < 8; bb++) acc[bb] = 0.f;
#pragma unroll
    for (int c = 0; c < 4; c++) {
        int kw = c * 128 + lane * 4;
        float4 w4 = *(const float4*)&W_head[(size_t)wrow * HDIM + kw];
#pragma unroll
        for (int bb = 0; bb < 8; bb++) {
            float4 a4 = *(const float4*)&h_s[bb][kw];
            acc[bb] = fmaf(w4.x, a4.x, acc[bb]);
            acc[bb] = fmaf(w4.y, a4.y, acc[bb]);
            acc[bb] = fmaf(w4.z, a4.z, acc[bb]);
            acc[bb] = fmaf(w4.w, a4.w, acc[bb]);
        }
    }
    float res = 0.f;
#pragma unroll
    for (int bb = 0; bb < 8; bb++) {
        float v = acc[bb];
        v += __shfl_xor_sync(0xffffffffu, v, 16);
        v += __shfl_xor_sync(0xffffffffu, v, 8);
        v += __shfl_xor_sync(0xffffffffu, v, 4);
        v += __shfl_xor_sync(0xffffffffu, v, 2);
        v += __shfl_xor_sync(0xffffffffu, v, 1);
        if (lane == bb) res = v;
    }
    if (lane < 8) {
        int b = bb0 + lane;
        float val = res + b_head[wrow];
        if (jj < HS)          g_rk[(b * NHEADS + n) * HS + jj] = val;
        else if (jj < 2 * HS) g_wk[(b * NHEADS + n) * HS + (jj - HS)] = val;
        else                  g_ws[b * NHEADS + n] = sigmoidf_(val);
    }
}

// ---------------- K3: logits — smem-staged tile, coalesced LDG, half-row threads ----------------
// grid (16, 32): 128-row chunk, batch. thread = (row = tid>>1, half = tid&1).
__global__ void __launch_bounds__(256) k_logits(const float* __restrict__ mem)
{
    __shared__ __align__(16) float key_s[NKEYS][64];
    __shared__ __align__(16) float tile[128 * TSTRIDE];  // padded rows
    __shared__ float wred[NKEYS][8];
    __shared__ float bmax[NKEYS];
    int tid = threadIdx.x;
    int b = blockIdx.y, chunk = blockIdx.x;

    // stage keys
    for (int idx = tid; idx < NKEYS * 64; idx += 256) {
        int key = idx >> 6, h = idx & 63, n = key & 3;
        key_s[key][h] = (key < 4) ? g_rk[(b * NHEADS + n) * HS + h]
                                  : g_wk[(b * NHEADS + n) * HS + h];
    }
    // stage 128x64 mem tile, fully coalesced (consecutive lanes -> consecutive 16B)
    {
        const float* src = &mem[((size_t)b * MS + chunk * 128) * HS];
#pragma unroll
        for (int it = 0; it < 8; it++) {
            int idx = it * 1024 + tid * 4;           // element index
            float4 v = *(const float4*)&src[idx];
            int row = idx >> 6, col = idx & 63;
            *(float4*)&tile[row * TSTRIDE + col] = v;
        }
    }
    __syncthreads();

    int r = tid >> 1, half = tid & 1;
    const float* trow = &tile[r * TSTRIDE + half * 32];
    float acc[NKEYS];
#pragma unroll
    for (int k = 0; k < NKEYS; k++) acc[k] = 0.f;
#pragma unroll
    for (int i = 0; i < 8; i++) {
        float4 a = *(const float4*)&trow[i * 4];
#pragma unroll
        for (int k = 0; k < NKEYS; k++) {
            float4 kv = *(const float4*)&key_s[k][half * 32 + i * 4];
            acc[k] = fmaf(a.x, kv.x, acc[k]);
            acc[k] = fmaf(a.y, kv.y, acc[k]);
            acc[k] = fmaf(a.z, kv.z, acc[k]);
            acc[k] = fmaf(a.w, kv.w, acc[k]);
        }
    }
    // pair reduce (halves of same row) + scale; both lanes end with full logit
    const float scale = 0.125f;
#pragma unroll
    for (int k = 0; k < NKEYS; k++) {
        float v = acc[k];
        v += __shfl_xor_sync(0xffffffffu, v, 1);
        acc[k] = v * scale;
    }
    // store: even lane -> keys 0..3, odd lane -> keys 4..7 (contiguous rows per plane)
    {
        int m = chunk * 128 + r;
        int kb = half * 4;
#pragma unroll
        for (int kk = 0; kk < 4; kk++)
            g_logits[((size_t)b * NKEYS + kb + kk) * MS + m] = acc[kb + kk];
    }

    // block softmax partials (each row duplicated on 2 lanes; dup is exact)
    int w = tid >> 5, lane = tid & 31;
#pragma unroll
    for (int k = 0; k < NKEYS; k++) {
        float v = acc[k];
        v = fmaxf(v, __shfl_xor_sync(0xffffffffu, v, 2));
        v = fmaxf(v, __shfl_xor_sync(0xffffffffu, v, 4));
        v = fmaxf(v, __shfl_xor_sync(0xffffffffu, v, 8));
        v = fmaxf(v, __shfl_xor_sync(0xffffffffu, v, 16));
        if (lane == 0) wred[k][w] = v;
    }
    __syncthreads();
    if (tid < NKEYS) {
        float v = wred[tid][0];
#pragma unroll
        for (int i = 1; i < 8; i++) v = fmaxf(v, wred[tid][i]);
        bmax[tid] = v;
    }
    __syncthreads();
#pragma unroll
    for (int k = 0; k < NKEYS; k++) {
        float v = expf(acc[k] - bmax[k]);
        v += __shfl_xor_sync(0xffffffffu, v, 1);
        v += __shfl_xor_sync(0xffffffffu, v, 2);
        v += __shfl_xor_sync(0xffffffffu, v, 4);
        v += __shfl_xor_sync(0xffffffffu, v, 8);
        v += __shfl_xor_sync(0xffffffffu, v, 16);
        if (lane == 0) wred[k][w] = v * 0.5f;   // each row counted twice (exact dup)
    }
    __syncthreads();
    if (tid < NKEYS) {
        float s = 0.f;
#pragma unroll
        for (int i = 0; i < 8; i++) s += wred[tid][i];
        g_pmax[(b * NKEYS + tid) * LCHUNKS + chunk] = bmax[tid];
        g_psum[(b * NKEYS + tid) * LCHUNKS + chunk] = s;
    }
}

// ---------------- K4: softmax finalize + single-pass read/update + last-block reduce ----------------
// grid (32, 32): chunk of 64 rows, batch.
__global__ void __launch_bounds__(256) k_attend(float* __restrict__ mem)
{
    __shared__ float gm[NKEYS], ginv[NKEYS];
    __shared__ float w_s[NKEYS][64];
    __shared__ float swk_s[NHEADS][64];
    __shared__ float sred[4][NHEADS * 64];
    __shared__ unsigned is_last;
    int tid = threadIdx.x;
    int chunk = blockIdx.x, b = blockIdx.y;

    if (tid < NKEYS) {
        const float* pm = &g_pmax[(b * NKEYS + tid) * LCHUNKS];
        const float* ps = &g_psum[(b * NKEYS + tid) * LCHUNKS];
        float m0 = pm[0];
#pragma unroll
        for (int i = 1; i < LCHUNKS; i++) m0 = fmaxf(m0, pm[i]);
        float s = 0.f;
#pragma unroll
        for (int i = 0; i < LCHUNKS; i++) s += expf(pm[i] - m0) * ps[i];
        gm[tid] = m0;
        ginv[tid] = 1.f / s;
    }
    {
        int n = tid >> 6, h = tid & 63;
        swk_s[n][h] = g_ws[b * NHEADS + n] * g_wk[(b * NHEADS + n) * HS + h];
    }
    __syncthreads();
    for (int idx = tid; idx < NKEYS * 64; idx += 256) {
        int key = idx >> 6, row = idx & 63;
        float lg = g_logits[((size_t)b * NKEYS + key) * MS + chunk * 64 + row];
        w_s[key][row] = expf(lg - gm[key]) * ginv[key];
    }
    __syncthreads();

    int h = tid & 63, ms = tid >> 6;
    float v[16];
    // front-batched loads (independent of FMA chain)
#pragma unroll
    for (int mi = 0; mi < 16; mi++) {
        int row = mi * 4 + ms;
        v[mi] = mem[((size_t)b * MS + chunk * 64 + row) * HS + h];
    }
    float acc[NHEADS] = {0.f, 0.f, 0.f, 0.f};
#pragma unroll
    for (int mi = 0; mi < 16; mi++) {
        int row = mi * 4 + ms;
#pragma unroll
        for (int n = 0; n < NHEADS; n++)
            acc[n] = fmaf(w_s[n][row], v[mi], acc[n]);
    }
#pragma unroll
    for (int mi = 0; mi < 16; mi++) {
        int row = mi * 4 + ms;
        float val = v[mi];
#pragma unroll
        for (int n = 0; n < NHEADS; n++)
            val = fmaf(w_s[4 + n][row], swk_s[n][h], val);
        mem[((size_t)b * MS + chunk * 64 + row) * HS + h] = val;
    }
#pragma unroll
    for (int n = 0; n < NHEADS; n++) sred[ms][n * 64 + h] = acc[n];
    __syncthreads();
    float tot = sred[0][tid] + sred[1][tid] + sred[2][tid] + sred[3][tid];
    g_rpart[((size_t)b * 32 + chunk) * 256 + tid] = tot;

    // deterministic last-block reduction into g_read
    __threadfence();
    if (tid == 0) is_last = (atomicAdd(&g_cnt[b], 1u) == 31u) ? 1u : 0u;
    __syncthreads();
    if (is_last) {
        if (tid == 0) g_cnt[b] = 0u;   // reset for next step / next replay
        __threadfence();
        float s = 0.f;
#pragma unroll
        for (int ch = 0; ch < 32; ch++)
            s += g_rpart[((size_t)b * 32 + ch) * 256 + tid];
        g_read[b * 256 + tid] = s;
    }
}

// ---------------- final: out(31) + state copy ----------------
__global__ void __launch_bounds__(256) k_last(
    const float* __restrict__ W_out, const float* __restrict__ b_out,
    float* __restrict__ out, float* __restrict__ dst_h, float* __restrict__ dst_c)
{
    if (blockIdx.x < 32) {
        out_body(W_out, b_out, out, g_h[0], TDIM - 1, blockIdx.x, blockIdx.y);
    } else if (blockIdx.y == 0) {
        int idx = (blockIdx.x - 32) * 256 + threadIdx.x;
        if (idx < BDIM * HDIM) {
            dst_h[idx] = g_h[0][idx];   // after 32 steps h lives in buffer 0
            dst_c[idx] = g_c[idx];
        }
    }
}

// ---------------- launch ----------------
extern "C" void kernel_launch(void* const* d_in, const int* in_sizes, int n_in,
                              void* d_out, int out_size)
{
    const float* x      = (const float*)d_in[0];
    const float* W_ih   = (const float*)d_in[1];
    const float* W_hh   = (const float*)d_in[2];
    const float* b_ih   = (const float*)d_in[3];
    const float* b_hh   = (const float*)d_in[4];
    const float* W_head = (const float*)d_in[5];
    const float* b_head = (const float*)d_in[6];
    const float* W_out  = (const float*)d_in[7];
    const float* b_out  = (const float*)d_in[8];

    float* out   = (float*)d_out;                 // (B, T, O)
    float* mem   = out + BDIM * TDIM * ODIM;      // (B, MS, HS)
    float* out_h = mem + (size_t)BDIM * MS * HS;  // (B, H)
    float* out_c = out_h + BDIM * HDIM;           // (B, H)

    k_init<<<(BDIM * MS * HS) / 256, 256>>>(mem);

    for (int t = 0; t < TDIM; t++) {
        int p = t & 1;
        int pn = p ^ 1;
        int gx = (t > 0) ? 96 : 64;   // fuse out(t-1) blocks when t>0
        k_lstm<<<dim3(gx, 4), 256>>>(x, W_ih, W_hh, b_ih, b_hh,
                                     W_out, b_out, out, p, t);
        k_head<<<dim3(65, 4), 256>>>(W_head, b_head, pn);
        k_logits<<<dim3(LCHUNKS, 32), 256>>>(mem);
        k_attend<<<dim3(32, 32), 256>>>(mem);
    }
    k_last<<<dim3(96, 4), 256>>>(W_out, b_out, out, out_h, out_c);
}